// round 6
// baseline (speedup 1.0000x reference)
#include <cuda_runtime.h>

#define NP  500000
#define NC  1000
#define DIM 128
#define NB  148                       // one partition block per SM
#define CH  ((NP + NB - 1) / NB)      // 3379 points per block chunk (fits u16 rank)

// Scratch (no allocations allowed -> __device__ globals)
__device__ int            g_counts[NC];
__device__ int            g_offsets[NC];
__device__ int            g_bh[NB * NC];   // per-block histogram, block-major
__device__ int            g_bb[NB * NC];   // per-(block,class) LOCAL base
__device__ unsigned short g_rank[NP];      // rank of point within (block,class)
__device__ int            g_sorted[NP];

// ---------------------------------------------------------------------------
// In-block dtype probe: y int64 (LE) => all odd 32-bit words of the first 256
// words are zero (classes < 1000). P(false positive | int32) ~ 1000^-128.
// ---------------------------------------------------------------------------
__device__ __forceinline__ int probe_is64(const int* __restrict__ y32, int* sflag) {
    if (threadIdx.x == 0) *sflag = 0;
    __syncthreads();
    if (threadIdx.x < 128) {
        int nz = (y32[2 * threadIdx.x + 1] != 0);
        unsigned any = __ballot_sync(0xFFFFFFFF, nz);
        if ((threadIdx.x & 31) == 0 && any) atomicOr(sflag, 1);
    }
    __syncthreads();
    return (*sflag == 0) ? 1 : 0;   // no nonzero odd words -> int64
}

// ---------------------------------------------------------------------------
// Kernel 1: per-block histogram over a contiguous chunk, privatized in smem.
// The atomicAdd RETURN VALUE is the point's rank within (block,class) -> saved
// to g_rank so the scatter pass needs no atomics at all.
// ---------------------------------------------------------------------------
__global__ void __launch_bounds__(512) blockhist_kernel(const int* __restrict__ y32) {
    __shared__ int h[NC];
    __shared__ int sflag;
    const int shift = probe_is64(y32, &sflag);
    for (int c = threadIdx.x; c < NC; c += 512) h[c] = 0;
    __syncthreads();
    const int b     = blockIdx.x;
    const int start = b * CH;
    const int end   = (start + CH < NP) ? start + CH : NP;
    for (int i = start + threadIdx.x; i < end; i += 512) {
        int c = y32[i << shift];
        g_rank[i] = (unsigned short)atomicAdd(&h[c], 1);
    }
    __syncthreads();
    for (int c = threadIdx.x; c < NC; c += 512)
        g_bh[b * NC + c] = h[c];
}

// ---------------------------------------------------------------------------
// Kernel 2: block-per-class parallel scan over the NB=148 block counts.
// 160 threads (5 warps); shfl warp-scan + cross-warp combine -> local
// exclusive base g_bb[t][c] and class total g_counts[c].
// ---------------------------------------------------------------------------
__global__ void __launch_bounds__(160) blockscan_kernel() {
    const int c    = blockIdx.x;
    const int t    = threadIdx.x;          // = block index b (when < NB)
    const int lane = t & 31;
    const int w    = t >> 5;               // 5 warps

    int v = (t < NB) ? g_bh[t * NC + c] : 0;

    int s = v;
    #pragma unroll
    for (int o = 1; o < 32; o <<= 1) {
        int n = __shfl_up_sync(0xFFFFFFFF, s, o);
        if (lane >= o) s += n;
    }

    __shared__ int wsum[5];
    __shared__ int wbase[5];
    if (lane == 31) wsum[w] = s;
    __syncthreads();

    if (w == 0 && lane < 5) {
        int ws = wsum[lane];
        int sc = ws;
        #pragma unroll
        for (int o = 1; o < 8; o <<= 1) {
            int n = __shfl_up_sync(0x0000001F, sc, o);
            if (lane >= o) sc += n;
        }
        wbase[lane] = sc - ws;             // exclusive warp base
        if (lane == 4) g_counts[c] = sc;   // class total
    }
    __syncthreads();

    if (t < NB)
        g_bb[t * NC + c] = (s - v) + wbase[w]; // local exclusive prefix
}

// ---------------------------------------------------------------------------
// Kernel 3: single block, shfl-hierarchy exclusive scan of 1000 class totals
// (warp scans + one cross-warp combine; 2 barriers total).
// ---------------------------------------------------------------------------
__global__ void __launch_bounds__(1024) scan_kernel() {
    const int t    = threadIdx.x;
    const int lane = t & 31;
    const int w    = t >> 5;               // 32 warps

    int v = (t < NC) ? g_counts[t] : 0;
    int s = v;
    #pragma unroll
    for (int o = 1; o < 32; o <<= 1) {
        int n = __shfl_up_sync(0xFFFFFFFF, s, o);
        if (lane >= o) s += n;
    }

    __shared__ int wsum[32];
    __shared__ int wbase[32];
    if (lane == 31) wsum[w] = s;
    __syncthreads();

    if (w == 0) {
        int ws = wsum[lane];
        int sc = ws;
        #pragma unroll
        for (int o = 1; o < 32; o <<= 1) {
            int n = __shfl_up_sync(0xFFFFFFFF, sc, o);
            if (lane >= o) sc += n;
        }
        wbase[lane] = sc - ws;
    }
    __syncthreads();

    if (t < NC) g_offsets[t] = (s - v) + wbase[w];
}

// ---------------------------------------------------------------------------
// Kernel 4: atomic-free scatter. Seed smem base[c] = local base + class
// offset, then pos = base[y[i]] + rank[i]. Pure streaming: coalesced y+rank
// loads, one scattered STG. No ATOMS dependence chain.
// ---------------------------------------------------------------------------
__global__ void __launch_bounds__(512) scatter_kernel(const int* __restrict__ y32) {
    __shared__ int base[NC];
    __shared__ int sflag;
    const int shift = probe_is64(y32, &sflag);
    const int b = blockIdx.x;
    for (int c = threadIdx.x; c < NC; c += 512)
        base[c] = g_bb[b * NC + c] + g_offsets[c];
    __syncthreads();
    const int start = b * CH;
    const int end   = (start + CH < NP) ? start + CH : NP;
    for (int i = start + threadIdx.x; i < end; i += 512) {
        int c   = y32[i << shift];
        int pos = base[c] + (int)g_rank[i];
        g_sorted[pos] = i;
    }
}

// ---------------------------------------------------------------------------
// Kernel 5: one block per class. 8 warps; warp = row-group, lane owns 4 dims
// (float4, 512B coalesced rows). 8 rows in flight per warp, 4-deep mid-tail,
// scalar final tail. Streaming loads. Reduce through shared, CMA update.
// ---------------------------------------------------------------------------
__global__ void __launch_bounds__(256) mean_kernel(
    const float* __restrict__ x,
    const float* __restrict__ centers,
    const float* __restrict__ counter,
    float*       __restrict__ out)
{
    const int c    = blockIdx.x;
    const int cnt  = g_counts[c];
    const int off  = g_offsets[c];
    const int lane = threadIdx.x & 31;
    const int grp  = threadIdx.x >> 5;

    float4 acc = make_float4(0.f, 0.f, 0.f, 0.f);

    int r = grp;
    for (; r + 56 < cnt; r += 64) {
        int idx[8];
        #pragma unroll
        for (int k = 0; k < 8; k++) idx[k] = g_sorted[off + r + 8 * k];
        #pragma unroll
        for (int k = 0; k < 8; k++) {
            float4 v = __ldcs(&((const float4*)(x + (size_t)idx[k] * DIM))[lane]);
            acc.x += v.x; acc.y += v.y; acc.z += v.z; acc.w += v.w;
        }
    }
    for (; r + 24 < cnt; r += 32) {
        int idx[4];
        #pragma unroll
        for (int k = 0; k < 4; k++) idx[k] = g_sorted[off + r + 8 * k];
        #pragma unroll
        for (int k = 0; k < 4; k++) {
            float4 v = __ldcs(&((const float4*)(x + (size_t)idx[k] * DIM))[lane]);
            acc.x += v.x; acc.y += v.y; acc.z += v.z; acc.w += v.w;
        }
    }
    for (; r < cnt; r += 8) {
        int i = g_sorted[off + r];
        float4 v = __ldcs(&((const float4*)(x + (size_t)i * DIM))[lane]);
        acc.x += v.x; acc.y += v.y; acc.z += v.z; acc.w += v.w;
    }

    __shared__ float4 sh[8][32];
    sh[grp][lane] = acc;
    __syncthreads();

    if (grp == 0) {
        float4 s = sh[0][lane];
        #pragma unroll
        for (int g = 1; g < 8; g++) {
            float4 v = sh[g][lane];
            s.x += v.x; s.y += v.y; s.z += v.z; s.w += v.w;
        }
        float4 cv = ((const float4*)(centers + c * DIM))[lane];
        float4 o;
        if (cnt > 0) {
            float ctr = counter[0];
            float inv = 1.0f / (ctr + 1.0f);
            float rn  = 1.0f / (float)cnt;
            o.x = (s.x * rn + cv.x * ctr) * inv;
            o.y = (s.y * rn + cv.y * ctr) * inv;
            o.z = (s.z * rn + cv.z * ctr) * inv;
            o.w = (s.w * rn + cv.w * ctr) * inv;
        } else {
            o = cv;  // class absent from batch: keep old center
        }
        ((float4*)(out + c * DIM))[lane] = o;
    }
}

// ---------------------------------------------------------------------------
// kernel_launch: graph-capturable, allocation-free, deterministic.
// Inputs (metadata order): x[NP*DIM] f32, y[NP] int64/int32, centers[NC*DIM]
// f32, counter[1] f32. Output: new centers [NC*DIM] f32.
// ---------------------------------------------------------------------------
extern "C" void kernel_launch(void* const* d_in, const int* in_sizes, int n_in,
                              void* d_out, int out_size) {
    const float* x       = (const float*)d_in[0];
    const int*   y32     = (const int*)d_in[1];
    const float* centers = (const float*)d_in[2];
    const float* counter = (const float*)d_in[3];
    float*       out     = (float*)d_out;

    blockhist_kernel<<<NB, 512>>>(y32);
    blockscan_kernel<<<NC, 160>>>();
    scan_kernel<<<1, 1024>>>();
    scatter_kernel<<<NB, 512>>>(y32);
    mean_kernel<<<NC, 256>>>(x, centers, counter, out);
}